// round 2
// baseline (speedup 1.0000x reference)
#include <cuda_runtime.h>
#include <cstdint>

#define Npts   20000
#define Msamp  5000
#define KNN    16
#define CIN    64
#define COUT   128
#define FDIM   (3 + CIN)          // 67
#define BN_EPS 1e-5f

// ---------------- device scratch (no allocs allowed) ----------------
__device__ float4             g_p4[Npts];          // x,y,z, |p|^2
__device__ float4             g_q4[Msamp];         // sampled q + |q|^2
__device__ int                g_nidx[Msamp * KNN];
__device__ float              g_h[Msamp * KNN * COUT];   // ~41 MB pre-BN activations
__device__ float              g_ps [Msamp * COUT];       // per-sample partial sums
__device__ float              g_pss[Msamp * COUT];       // per-sample partial sumsq
__device__ float              g_mean[COUT];
__device__ float              g_rstd[COUT];
__device__ float              g_np_scratch[Msamp * 3];   // fallback if n_p not in output

// ---------------- pack: p [N,3] -> float4 with |p|^2 ----------------
__global__ void pack_kernel(const float* __restrict__ p) {
    int i = blockIdx.x * blockDim.x + threadIdx.x;
    if (i < Npts) {
        float x = p[3 * i], y = p[3 * i + 1], z = p[3 * i + 2];
        float pp = __fadd_rn(__fadd_rn(__fmul_rn(x, x), __fmul_rn(y, y)), __fmul_rn(z, z));
        g_p4[i] = make_float4(x, y, z, pp);
    }
}

// ---------------- FPS: single block, dist register-resident ----------------
// Exactly replicates: dist=min(dist, |p - p[last]|^2) with ((dx^2+dy^2)+dz^2),
// argmax with first-index tie-break. (Verified bit-exact in R1.)
__global__ __launch_bounds__(1024, 1) void fps_kernel(float* __restrict__ out_np) {
    __shared__ float4 s_last;
    __shared__ unsigned long long s_w[32];
    const int t = threadIdx.x;

    float dist[20];
#pragma unroll
    for (int j = 0; j < 20; j++) dist[j] = 1e10f;

    if (t == 0) {
        float4 P = g_p4[0];
        s_last = P;
        out_np[0] = P.x; out_np[1] = P.y; out_np[2] = P.z;
        g_q4[0] = P;
    }
    __syncthreads();

    for (int i = 1; i < Msamp; i++) {
        const float lx = s_last.x, ly = s_last.y, lz = s_last.z;
        float bd = -1.0f; int bi = 0;
#pragma unroll
        for (int j = 0; j < 19; j++) {
            int idx = t + j * 1024;
            float4 P = __ldg(&g_p4[idx]);
            float dx = __fsub_rn(P.x, lx), dy = __fsub_rn(P.y, ly), dz = __fsub_rn(P.z, lz);
            float d = __fadd_rn(__fadd_rn(__fmul_rn(dx, dx), __fmul_rn(dy, dy)), __fmul_rn(dz, dz));
            float nd = fminf(dist[j], d);
            dist[j] = nd;
            if (nd > bd) { bd = nd; bi = idx; }
        }
        {   // tail chunk j = 19 (only threads t < 544 valid)
            int idx = t + 19 * 1024;
            if (idx < Npts) {
                float4 P = __ldg(&g_p4[idx]);
                float dx = __fsub_rn(P.x, lx), dy = __fsub_rn(P.y, ly), dz = __fsub_rn(P.z, lz);
                float d = __fadd_rn(__fadd_rn(__fmul_rn(dx, dx), __fmul_rn(dy, dy)), __fmul_rn(dz, dz));
                float nd = fminf(dist[19], d);
                dist[19] = nd;
                if (nd > bd) { bd = nd; bi = idx; }
            }
        }
        // key: (dist_bits << 32) | ~idx  -> max key == max dist, tie -> lowest idx
        unsigned long long key =
            ((unsigned long long)__float_as_uint(bd) << 32) | (unsigned)(0xFFFFFFFFu - (unsigned)bi);
#pragma unroll
        for (int off = 16; off; off >>= 1) {
            unsigned long long o = __shfl_down_sync(0xFFFFFFFFu, key, off);
            if (o > key) key = o;
        }
        if ((t & 31) == 0) s_w[t >> 5] = key;
        __syncthreads();
        if (t < 32) {
            unsigned long long k2 = s_w[t];
#pragma unroll
            for (int off = 16; off; off >>= 1) {
                unsigned long long o = __shfl_down_sync(0xFFFFFFFFu, k2, off);
                if (o > k2) k2 = o;
            }
            if (t == 0) {
                int idx = (int)(0xFFFFFFFFu - (unsigned)(k2 & 0xFFFFFFFFull));
                float4 P = __ldg(&g_p4[idx]);
                s_last = P;
                out_np[3 * i] = P.x; out_np[3 * i + 1] = P.y; out_np[3 * i + 2] = P.z;
                g_q4[i] = P;
            }
        }
        __syncthreads();
    }
}

// ---------------- kNN: warp per query, threshold + ballot buffer ----------------
#define INFKEY 0xFFFFFFFFFFFFFFFFull

__device__ __forceinline__ void knn_merge(unsigned long long* cand, int lane,
                                          unsigned long long& cur,
                                          unsigned long long& thr, int& cnt) {
    if (lane < 16) cand[64 + lane] = cur;
#pragma unroll
    for (int s = lane; s < 64; s += 32) if (s >= cnt) cand[s] = INFKEY;
    __syncwarp();
    unsigned long long picked = INFKEY, last = INFKEY;
#pragma unroll 1
    for (int r = 0; r < 16; r++) {
        unsigned long long a = cand[lane];
        unsigned long long b = cand[lane + 32];
        unsigned long long c = (lane < 16) ? cand[64 + lane] : INFKEY;
        unsigned long long v = a < b ? a : b;
        v = v < c ? v : c;
#pragma unroll
        for (int off = 16; off; off >>= 1) {
            unsigned long long o = __shfl_down_sync(0xFFFFFFFFu, v, off);
            if (o < v) v = o;
        }
        v = __shfl_sync(0xFFFFFFFFu, v, 0);
        if (a == v)                       cand[lane]      = INFKEY;
        else if (b == v)                  cand[lane + 32] = INFKEY;
        else if (lane < 16 && c == v)     cand[64 + lane] = INFKEY;
        __syncwarp();
        if (lane == r) picked = v;
        last = v;
    }
    cur = picked; thr = last; cnt = 0;
    __syncwarp();
}

__global__ __launch_bounds__(128) void knn_kernel() {
    __shared__ unsigned long long cand_s[4][80];
    const int warp = threadIdx.x >> 5, lane = threadIdx.x & 31;
    const int m = blockIdx.x * 4 + warp;
    unsigned long long* cand = cand_s[warp];

    const float4 Q = g_q4[m];
    unsigned long long cur = INFKEY, thr = INFKEY;
    int cnt = 0;

#pragma unroll 1
    for (int s = 0; s < Npts / 32; s++) {
        int idx = lane + 32 * s;
        float4 P = __ldg(&g_p4[idx]);
        // reference: qq - 2*(q@p.T) + pp, where the matmul dot is an FMA chain
        // (XLA dot_general lowering): fma(q2,p2, fma(q1,p1, q0*p0))
        float dot = __fmaf_rn(Q.z, P.z, __fmaf_rn(Q.y, P.y, __fmul_rn(Q.x, P.x)));
        float d = __fadd_rn(__fsub_rn(Q.w, __fmul_rn(2.0f, dot)), P.w);
        unsigned ub = __float_as_uint(d);
        ub ^= (ub >> 31) ? 0xFFFFFFFFu : 0x80000000u;   // order-preserving float->uint
        unsigned long long k = ((unsigned long long)ub << 32) | (unsigned)idx;
        bool pred = k < thr;
        unsigned bal = __ballot_sync(0xFFFFFFFFu, pred);
        if (pred) {
            int pos = cnt + __popc(bal & ((1u << lane) - 1u));
            cand[pos] = k;
        }
        cnt += __popc(bal);
        if (cnt >= 32) knn_merge(cand, lane, cur, thr, cnt);
    }
    if (cnt > 0) knn_merge(cand, lane, cur, thr, cnt);
    if (lane < 16) g_nidx[m * KNN + lane] = (int)(unsigned)(cur & 0xFFFFFFFFull);
}

// ---------------- gather + linear (feat @ W), stash h + partial BN sums ----------------
__global__ __launch_bounds__(128) void gemm_kernel(const float* __restrict__ x,
                                                   const float* __restrict__ W) {
    __shared__ float sW[FDIM * COUT];       // 67*128*4 = 34304 B
    __shared__ float sF[KNN][FDIM + 1];
    const int m = blockIdx.x, t = threadIdx.x;

    for (int i = t; i < FDIM * COUT; i += 128) sW[i] = W[i];
    const float4 Q = g_q4[m];
    for (int e = t; e < KNN * FDIM; e += 128) {
        int r = e / FDIM, j = e - r * FDIM;
        int n = g_nidx[m * KNN + r];
        float v;
        if (j < 3) {
            float4 P = g_p4[n];
            v = (j == 0) ? __fsub_rn(P.x, Q.x) : (j == 1) ? __fsub_rn(P.y, Q.y)
                                                          : __fsub_rn(P.z, Q.z);
        } else {
            v = __ldg(&x[n * CIN + (j - 3)]);
        }
        sF[r][j] = v;
    }
    __syncthreads();

    float acc[KNN];
#pragma unroll
    for (int r = 0; r < KNN; r++) acc[r] = 0.0f;
#pragma unroll 1
    for (int j = 0; j < FDIM; j++) {
        float wv = sW[j * COUT + t];
#pragma unroll
        for (int r = 0; r < KNN; r++) acc[r] = fmaf(sF[r][j], wv, acc[r]);
    }
    float s1 = 0.0f, s2 = 0.0f;
#pragma unroll
    for (int r = 0; r < KNN; r++) {
        g_h[(m * KNN + r) * COUT + t] = acc[r];
        s1 += acc[r];
        s2 = fmaf(acc[r], acc[r], s2);
    }
    g_ps [m * COUT + t] = s1;
    g_pss[m * COUT + t] = s2;
}

// ---------------- deterministic BN stats reduction ----------------
__global__ __launch_bounds__(256) void stats_kernel() {
    __shared__ float s1[256], s2[256];
    const int c = blockIdx.x, t = threadIdx.x;
    float a = 0.0f, b = 0.0f;
    for (int m = t; m < Msamp; m += 256) {
        a += g_ps [m * COUT + c];
        b += g_pss[m * COUT + c];
    }
    s1[t] = a; s2[t] = b;
    __syncthreads();
    for (int o = 128; o; o >>= 1) {
        if (t < o) { s1[t] += s1[t + o]; s2[t] += s2[t + o]; }
        __syncthreads();
    }
    if (t == 0) {
        const float inv_n = 1.0f / (float)(Msamp * KNN);
        float mean = s1[0] * inv_n;
        float var  = fmaxf(s2[0] * inv_n - mean * mean, 0.0f);
        g_mean[c] = mean;
        g_rstd[c] = rsqrtf(var + BN_EPS);
    }
}

// ---------------- BN + ReLU + maxpool over k ----------------
__global__ __launch_bounds__(128) void final_kernel(const float* __restrict__ gamma,
                                                    const float* __restrict__ beta,
                                                    float* __restrict__ out_x,
                                                    float* __restrict__ out_no) {
    const int m = blockIdx.x, c = threadIdx.x;
    const float mean = g_mean[c], inv = g_rstd[c];
    const float gm = __ldg(&gamma[c]), bt = __ldg(&beta[c]);
    float mx = 0.0f;
#pragma unroll
    for (int r = 0; r < KNN; r++) {
        float h = g_h[(m * KNN + r) * COUT + c];
        float y = (h - mean) * inv * gm + bt;
        y = fmaxf(y, 0.0f);
        mx = fmaxf(mx, y);
    }
    out_x[m * COUT + c] = mx;
    if (out_no != nullptr && m == 0 && c == 0) *out_no = (float)Msamp;
}

// ---------------- launch ----------------
extern "C" void kernel_launch(void* const* d_in, const int* in_sizes, int n_in,
                              void* d_out, int out_size) {
    const float* p     = (const float*)d_in[0];
    const float* x     = (const float*)d_in[1];
    const float* W     = (const float*)d_in[3];
    const float* gamma = (const float*)d_in[4];
    const float* beta  = (const float*)d_in[5];
    float* out = (float*)d_out;

    const int np_elems = Msamp * 3;           // 15000
    const int x_elems  = Msamp * COUT;        // 640000

    float* np_dst = out;
    float* x_dst  = out + np_elems;
    float* no_dst = nullptr;
    if (out_size >= np_elems + x_elems + 1) {
        no_dst = out + np_elems + x_elems;
    } else if (out_size == x_elems) {        // fallback: only x_out in output
        float* scr; cudaGetSymbolAddress((void**)&scr, g_np_scratch);
        np_dst = scr;
        x_dst  = out;
    }

    pack_kernel <<<(Npts + 255) / 256, 256>>>(p);
    fps_kernel  <<<1, 1024>>>(np_dst);
    knn_kernel  <<<Msamp / 4, 128>>>();
    gemm_kernel <<<Msamp, 128>>>(x, W);
    stats_kernel<<<COUT, 256>>>();
    final_kernel<<<Msamp, 128>>>(gamma, beta, x_dst, no_dst);
}